// round 10
// baseline (speedup 1.0000x reference)
#include <cuda_runtime.h>
#include <cuda_fp16.h>
#include <cstdint>
#include <cstddef>

#define B_   8
#define C_   192
#define HW_  16384
#define D_   64

typedef unsigned long long u64;
typedef unsigned int u32;

// ---------------- static device scratch (allocation-free rule) ----------------
__device__ __half g_G[(size_t)B_ * HW_ * 192];     // gate pre-activations, fp16 (50MB, L2-resident)
__device__ float  g_Hs[2][(size_t)B_ * HW_ * D_];  // per-axis hidden sum (fwd+bwd)
__device__ float  g_Wc[C_ * 192];                  // folded input weights [c][g]
__device__ float  g_bc[192];
__device__ float  g_Wot[D_ * C_];                  // Wo^T [d][c]

// ---------------- f32x2 helpers ----------------
__device__ __forceinline__ void fma2(u64 &acc, u64 a, u64 b) {
    asm("fma.rn.f32x2 %0, %1, %2, %0;" : "+l"(acc) : "l"(a), "l"(b));
}
__device__ __forceinline__ u64 pack2(float x, float y) {
    u64 r; asm("mov.b64 %0, {%1, %2};" : "=l"(r) : "f"(x), "f"(y)); return r;
}
__device__ __forceinline__ float2 unpack2(u64 v) {
    float2 r; asm("mov.b64 {%0, %1}, %2;" : "=f"(r.x), "=f"(r.y) : "l"(v)); return r;
}
__device__ __forceinline__ float sigm(float x) { return 1.f / (1.f + __expf(-x)); }
__device__ __forceinline__ u32 h2u(__half2 h) { return *reinterpret_cast<u32*>(&h); }

// ---------------- kernel 1: fold weights ----------------
__global__ void prep_kernel(const float* __restrict__ Wi, const float* __restrict__ bi,
                            const float* __restrict__ Wih, const float* __restrict__ bih,
                            const float* __restrict__ Wo) {
    const int bid = blockIdx.x;
    const int c = threadIdx.x;
    if (bid < 192) {
        const int g = bid;
        float acc = 0.f;
        #pragma unroll 8
        for (int d = 0; d < 64; d++) acc += Wih[g * 64 + d] * Wi[d * 192 + c];
        g_Wc[c * 192 + g] = acc;
        if (c == 0) {
            float s = bih[g];
            for (int d = 0; d < 64; d++) s += Wih[g * 64 + d] * bi[d];
            g_bc[g] = s;
        }
    } else {
        const int d = bid - 192;
        g_Wot[d * 192 + c] = Wo[c * 64 + d];
    }
}

// ---------------- kernel 2: G = Wc @ x + bc  (f32x2, fp16 stores) ----------------
__global__ void __launch_bounds__(256) g_gemm_kernel(const float* __restrict__ x) {
    const int pblk = blockIdx.y;          // 0..511
    const int b  = pblk >> 6;
    const int p0 = (pblk & 63) * 256;
    const int g0 = blockIdx.x * 64;
    const int tid = threadIdx.x;
    const int tx = tid & 31;
    const int ty = tid >> 5;

    __shared__ __align__(16) float  sX[16][256];
    __shared__ __align__(16) float2 sWd[16][64];

    u64 acc[2][2][8];
    #pragma unroll
    for (int h = 0; h < 2; h++)
        #pragma unroll
        for (int p = 0; p < 2; p++)
            #pragma unroll
            for (int j = 0; j < 8; j++) acc[h][p][j] = 0ULL;

    const float* xb = x + (size_t)b * C_ * HW_ + p0;

    for (int c0i = 0; c0i < 192; c0i += 16) {
        #pragma unroll
        for (int i = 0; i < 4; i++) {
            int lin = tid + i * 256;
            int cc = lin >> 6, q4 = lin & 63;
            ((float4*)sX[cc])[q4] = *(const float4*)(xb + (size_t)(c0i + cc) * HW_ + q4 * 4);
        }
        #pragma unroll
        for (int i = 0; i < 4; i++) {
            int lin = tid + i * 256;
            int cc = lin >> 6, gg = lin & 63;
            float w = g_Wc[(c0i + cc) * 192 + g0 + gg];
            sWd[cc][gg] = make_float2(w, w);
        }
        __syncthreads();
        #pragma unroll
        for (int cc = 0; cc < 16; cc++) {
            longlong2 xA = *(const longlong2*)&sX[cc][4 * tx];
            longlong2 xB = *(const longlong2*)&sX[cc][128 + 4 * tx];
            const longlong2* wp = (const longlong2*)&sWd[cc][8 * ty];
            longlong2 w01 = wp[0], w23 = wp[1], w45 = wp[2], w67 = wp[3];
            u64 wd[8] = { (u64)w01.x, (u64)w01.y, (u64)w23.x, (u64)w23.y,
                          (u64)w45.x, (u64)w45.y, (u64)w67.x, (u64)w67.y };
            #pragma unroll
            for (int j = 0; j < 8; j++) {
                fma2(acc[0][0][j], wd[j], (u64)xA.x);
                fma2(acc[0][1][j], wd[j], (u64)xA.y);
                fma2(acc[1][0][j], wd[j], (u64)xB.x);
                fma2(acc[1][1][j], wd[j], (u64)xB.y);
            }
        }
        __syncthreads();
    }

    float bc[8];
    *(float4*)&bc[0] = *(const float4*)&g_bc[g0 + 8 * ty];
    *(float4*)&bc[4] = *(const float4*)&g_bc[g0 + 8 * ty + 4];

    #pragma unroll
    for (int h = 0; h < 2; h++) {
        #pragma unroll
        for (int p = 0; p < 2; p++) {
            const size_t q = (size_t)b * HW_ + p0 + h * 128 + 4 * tx + 2 * p;
            float2 v[8];
            #pragma unroll
            for (int j = 0; j < 8; j++) v[j] = unpack2(acc[h][p][j]);
            uint4 s0, s1;
            s0.x = h2u(__floats2half2_rn(v[0].x + bc[0], v[1].x + bc[1]));
            s0.y = h2u(__floats2half2_rn(v[2].x + bc[2], v[3].x + bc[3]));
            s0.z = h2u(__floats2half2_rn(v[4].x + bc[4], v[5].x + bc[5]));
            s0.w = h2u(__floats2half2_rn(v[6].x + bc[6], v[7].x + bc[7]));
            s1.x = h2u(__floats2half2_rn(v[0].y + bc[0], v[1].y + bc[1]));
            s1.y = h2u(__floats2half2_rn(v[2].y + bc[2], v[3].y + bc[3]));
            s1.z = h2u(__floats2half2_rn(v[4].y + bc[4], v[5].y + bc[5]));
            s1.w = h2u(__floats2half2_rn(v[6].y + bc[6], v[7].y + bc[7]));
            *(uint4*)(&g_G[q * 192 + g0 + 8 * ty])       = s0;
            *(uint4*)(&g_G[(q + 1) * 192 + g0 + 8 * ty]) = s1;
        }
    }
}

// ---------------- kernel 3: GRU scans — split-row, pair-shuffle, double-buffered ----------------
// 1024 blocks (both axes), 384 threads, 2 lines x (fwd+bwd) = 4 seqs per block.
// Thread tid: g = tid>>1 (gate row), half = tid&1 (owns W_hh[g][32*half..+32), 32 regs).
// Half-dot chains (16-deep) per seq; pair combined via shfl_xor(1); hg via smem.
// Gate items: 256 = 4 seqs x 64 d -> thread tid<256: s=tid>>6, d=tid&63.
// h double-buffered in smem; Hs accumulated in smem line buffers, flushed at end.
__global__ void __launch_bounds__(384, 2) scan_kernel(const float* __restrict__ Whh,
                                                      const float* __restrict__ bhh) {
    extern __shared__ __align__(16) float smem[];
    float* h2  = smem;                 // [2][4][64]  double-buffered hidden
    float* hg  = smem + 512;           // [4][192]
    float* buf = smem + 512 + 768;     // [2][128][64] line accumulators

    const int blk   = blockIdx.x;
    const int axis  = blk >> 9;
    const int lb    = (blk & 511) * 2;
    const int b     = lb >> 7;
    const int lane0 = lb & 127;
    const int tid   = threadIdx.x;
    const int g     = tid >> 1;
    const int half  = tid & 1;

    // 32 weights (16 u64): W_hh[g][32*half .. 32*half+31]; fully coalesced load.
    u64 w2[16];
    {
        const float2* wr = (const float2*)(Whh + g * 64 + half * 32);
        #pragma unroll
        for (int k = 0; k < 16; k++) { float2 w = wr[k]; w2[k] = pack2(w.x, w.y); }
    }
    const float bh = bhh[g];

    for (int i = tid; i < 512; i += 384) h2[i] = 0.f;
    __syncthreads();

    const __half* Gb = g_G + (size_t)b * HW_ * 192;
    float* outS = g_Hs[axis] + (size_t)b * HW_ * 64;

    // gate item (threads tid<256): s = tid>>6, d = tid&63
    const bool gate_on = (tid < 256);
    const int s_it  = (tid >> 6) & 3;
    const int d_it  = tid & 63;
    const int dir   = s_it & 1;
    const int li    = s_it >> 1;
    const int line  = lane0 + li;
    const int pm    = axis ? 128 : 1;
    const int pa    = axis ? line : line * 128;

    // initial G load (t=0)
    float cx = 0.f, cz = 0.f, cn = 0.f;
    if (gate_on) {
        const int tt = dir ? 127 : 0;
        const __half* Gp = Gb + (size_t)(pa + tt * pm) * 192 + d_it;
        cx = __half2float(__ldg(Gp));
        cz = __half2float(__ldg(Gp + 64));
        cn = __half2float(__ldg(Gp + 128));
    }

    const int half32 = half * 32;

    for (int t = 0; t < 128; t++) {
        const int cur = (t & 1) * 256;
        const int nxt = 256 - cur;

        // ---- prefetch G for step t+1 (overlaps matvec) ----
        float nx = 0.f, nz = 0.f, nn = 0.f;
        if (gate_on) {
            const int tq = (t + 1) & 127;
            const int tt = dir ? 127 - tq : tq;
            const __half* Gp = Gb + (size_t)(pa + tt * pm) * 192 + d_it;
            nx = __half2float(__ldg(Gp));
            nz = __half2float(__ldg(Gp + 64));
            nn = __half2float(__ldg(Gp + 128));
        }

        // ---- half-dot matvec: 4 independent 16-deep fma2 chains ----
        u64 a0 = 0ULL, a1 = 0ULL, a2 = 0ULL, a3 = 0ULL;
        const longlong2* hv0 = (const longlong2*)(h2 + cur + 0 * 64 + half32);
        const longlong2* hv1 = (const longlong2*)(h2 + cur + 1 * 64 + half32);
        const longlong2* hv2 = (const longlong2*)(h2 + cur + 2 * 64 + half32);
        const longlong2* hv3 = (const longlong2*)(h2 + cur + 3 * 64 + half32);
        #pragma unroll
        for (int kk = 0; kk < 8; kk++) {
            longlong2 q0 = hv0[kk], q1 = hv1[kk], q2 = hv2[kk], q3 = hv3[kk];
            const u64 wA = w2[2 * kk], wB = w2[2 * kk + 1];
            fma2(a0, wA, (u64)q0.x); fma2(a1, wA, (u64)q1.x);
            fma2(a2, wA, (u64)q2.x); fma2(a3, wA, (u64)q3.x);
            fma2(a0, wB, (u64)q0.y); fma2(a1, wB, (u64)q1.y);
            fma2(a2, wB, (u64)q2.y); fma2(a3, wB, (u64)q3.y);
        }
        {
            float2 f;
            float p0, p1, p2, p3;
            f = unpack2(a0); p0 = f.x + f.y;
            f = unpack2(a1); p1 = f.x + f.y;
            f = unpack2(a2); p2 = f.x + f.y;
            f = unpack2(a3); p3 = f.x + f.y;
            p0 += __shfl_xor_sync(0xFFFFFFFFu, p0, 1);
            p1 += __shfl_xor_sync(0xFFFFFFFFu, p1, 1);
            p2 += __shfl_xor_sync(0xFFFFFFFFu, p2, 1);
            p3 += __shfl_xor_sync(0xFFFFFFFFu, p3, 1);
            if (half == 0) {
                hg[0 * 192 + g] = bh + p0;
                hg[1 * 192 + g] = bh + p1;
                hg[2 * 192 + g] = bh + p2;
                hg[3 * 192 + g] = bh + p3;
            }
        }
        __syncthreads();

        // ---- gate phase (one item per thread, tid<256) ----
        if (gate_on) {
            const int tt = dir ? 127 - t : t;
            const float hr = hg[s_it * 192 + d_it];
            const float hz = hg[s_it * 192 + 64 + d_it];
            const float hn = hg[s_it * 192 + 128 + d_it];
            const float rr = sigm(cx + hr);
            const float zz = sigm(cz + hz);
            const float pre = cn + rr * hn;
            const float nv = 2.f / (1.f + __expf(-2.f * pre)) - 1.f;   // tanh
            const float hnew = (1.f - zz) * nv + zz * h2[cur + s_it * 64 + d_it];
            h2[nxt + s_it * 64 + d_it] = hnew;
            float* o = buf + li * 8192 + tt * 64 + d_it;
            if (t < 64) *o = hnew;        // first contribution to this pixel
            else        *o = *o + hnew;   // second contribution (smem accumulate)
        }
        __syncthreads();

        cx = nx; cz = nz; cn = nn;
    }

    // ---- flush line buffers to g_Hs (coalesced) ----
    for (int i = tid; i < 2 * 128 * 64; i += 384) {
        const int lii = i >> 13;
        const int rem = i & 8191;
        const int tt = rem >> 6;
        const int d = rem & 63;
        const int ln = lane0 + lii;
        const int p = axis ? (tt * 128 + ln) : (ln * 128 + tt);
        outS[(size_t)p * 64 + d] = buf[i];
    }
}

// ---------------- kernel 4: out = Wo @ avg(h) + bo ----------------
__global__ void __launch_bounds__(256) out_gemm_kernel(const float* __restrict__ bo,
                                                       float* __restrict__ out) {
    const int bx = blockIdx.x;
    const int b  = bx >> 8;
    const int p0 = (bx & 255) * 64;
    const int c0 = blockIdx.y * 64;
    const int tid = threadIdx.x;
    const int tx = tid & 15;
    const int ty = tid >> 4;

    __shared__ __align__(16) float sH[64][66];
    __shared__ __align__(16) float sW[64][64];

    const size_t base = ((size_t)b * HW_ + p0) * 64;
    const float* hH = g_Hs[0] + base;
    const float* hV = g_Hs[1] + base;

    #pragma unroll
    for (int i = 0; i < 16; i++) {
        int lin = tid + i * 256;
        int pp = lin >> 6, dd = lin & 63;
        sH[dd][pp] = 0.25f * (hH[(size_t)pp * 64 + dd] + hV[(size_t)pp * 64 + dd]);
    }
    #pragma unroll
    for (int i = 0; i < 16; i++) {
        int lin = tid + i * 256;
        int dd = lin >> 6, cc = lin & 63;
        sW[dd][cc] = g_Wot[dd * 192 + c0 + cc];
    }
    __syncthreads();

    u64 acc[4][2];
    #pragma unroll
    for (int j = 0; j < 4; j++) { acc[j][0] = 0ULL; acc[j][1] = 0ULL; }

    #pragma unroll
    for (int dd = 0; dd < 64; dd++) {
        const u64* ap = (const u64*)&sH[dd][4 * tx];
        u64 aLo = ap[0], aHi = ap[1];
        float4 wv = *(const float4*)&sW[dd][4 * ty];
        u64 wd[4] = { pack2(wv.x, wv.x), pack2(wv.y, wv.y),
                      pack2(wv.z, wv.z), pack2(wv.w, wv.w) };
        #pragma unroll
        for (int j = 0; j < 4; j++) {
            fma2(acc[j][0], wd[j], aLo);
            fma2(acc[j][1], wd[j], aHi);
        }
    }

    #pragma unroll
    for (int j = 0; j < 4; j++) {
        const int c = c0 + 4 * ty + j;
        const float bv = bo[c];
        float2 lo = unpack2(acc[j][0]), hi = unpack2(acc[j][1]);
        float4 v = make_float4(lo.x + bv, lo.y + bv, hi.x + bv, hi.y + bv);
        *(float4*)&out[((size_t)b * 192 + c) * HW_ + p0 + 4 * tx] = v;
    }
}

// ---------------- launch ----------------
extern "C" void kernel_launch(void* const* d_in, const int* in_sizes, int n_in,
                              void* d_out, int out_size) {
    const float* x   = (const float*)d_in[0];
    const float* Wi  = (const float*)d_in[1];
    const float* bi  = (const float*)d_in[2];
    const float* Wih = (const float*)d_in[3];
    const float* Whh = (const float*)d_in[4];
    const float* bih = (const float*)d_in[5];
    const float* bhh = (const float*)d_in[6];
    const float* Wo  = (const float*)d_in[7];
    const float* bo  = (const float*)d_in[8];
    float* out = (float*)d_out;

    const int SCAN_SMEM = (512 + 768 + 2 * 128 * 64) * 4;   // 70656 B
    cudaFuncSetAttribute(scan_kernel, cudaFuncAttributeMaxDynamicSharedMemorySize, SCAN_SMEM);

    prep_kernel<<<256, 192>>>(Wi, bi, Wih, bih, Wo);
    g_gemm_kernel<<<dim3(3, 512), 256>>>(x);
    scan_kernel<<<1024, 384, SCAN_SMEM>>>(Whh, bhh);
    out_gemm_kernel<<<dim3(2048, 3), 256>>>(bo, out);
}

// round 11
// speedup vs baseline: 1.0542x; 1.0542x over previous
#include <cuda_runtime.h>
#include <cuda_fp16.h>
#include <cstdint>
#include <cstddef>

#define B_   8
#define C_   192
#define HW_  16384
#define D_   64

typedef unsigned long long u64;
typedef unsigned int u32;

// ---------------- static device scratch (allocation-free rule) ----------------
__device__ __half g_G[(size_t)B_ * HW_ * 192];     // gate pre-activations, fp16 (50MB, L2-resident)
__device__ float  g_Hs[2][(size_t)B_ * HW_ * D_];  // per-axis hidden sum (fwd+bwd)
__device__ float  g_Wc[C_ * 192];                  // folded input weights [c][g]
__device__ float  g_bc[192];
__device__ float  g_Wot[D_ * C_];                  // Wo^T [d][c]

// ---------------- f32x2 / fast-math helpers ----------------
__device__ __forceinline__ void fma2(u64 &acc, u64 a, u64 b) {
    asm("fma.rn.f32x2 %0, %1, %2, %0;" : "+l"(acc) : "l"(a), "l"(b));
}
__device__ __forceinline__ u64 pack2(float x, float y) {
    u64 r; asm("mov.b64 %0, {%1, %2};" : "=l"(r) : "f"(x), "f"(y)); return r;
}
__device__ __forceinline__ float2 unpack2(u64 v) {
    float2 r; asm("mov.b64 {%0, %1}, %2;" : "=f"(r.x), "=f"(r.y) : "l"(v)); return r;
}
__device__ __forceinline__ float sigm(float x) {
    float e; asm("ex2.approx.f32 %0, %1;" : "=f"(e) : "f"(-1.442695041f * x));
    float r; asm("rcp.approx.f32 %0, %1;" : "=f"(r) : "f"(1.f + e));
    return r;
}
__device__ __forceinline__ float tanhx(float x) {
    float r; asm("tanh.approx.f32 %0, %1;" : "=f"(r) : "f"(x)); return r;
}
__device__ __forceinline__ u32 h2u(__half2 h) { return *reinterpret_cast<u32*>(&h); }

// ---------------- kernel 1: fold weights ----------------
__global__ void prep_kernel(const float* __restrict__ Wi, const float* __restrict__ bi,
                            const float* __restrict__ Wih, const float* __restrict__ bih,
                            const float* __restrict__ Wo) {
    const int bid = blockIdx.x;
    const int c = threadIdx.x;
    if (bid < 192) {
        const int g = bid;
        float acc = 0.f;
        #pragma unroll 8
        for (int d = 0; d < 64; d++) acc += Wih[g * 64 + d] * Wi[d * 192 + c];
        g_Wc[c * 192 + g] = acc;
        if (c == 0) {
            float s = bih[g];
            for (int d = 0; d < 64; d++) s += Wih[g * 64 + d] * bi[d];
            g_bc[g] = s;
        }
    } else {
        const int d = bid - 192;
        g_Wot[d * 192 + c] = Wo[c * 64 + d];
    }
}

// ---------------- kernel 2: G = Wc @ x + bc  (f32x2, fp16 stores) ----------------
__global__ void __launch_bounds__(256) g_gemm_kernel(const float* __restrict__ x) {
    const int pblk = blockIdx.y;          // 0..511
    const int b  = pblk >> 6;
    const int p0 = (pblk & 63) * 256;
    const int g0 = blockIdx.x * 64;
    const int tid = threadIdx.x;
    const int tx = tid & 31;
    const int ty = tid >> 5;

    __shared__ __align__(16) float  sX[16][256];
    __shared__ __align__(16) float2 sWd[16][64];

    u64 acc[2][2][8];
    #pragma unroll
    for (int h = 0; h < 2; h++)
        #pragma unroll
        for (int p = 0; p < 2; p++)
            #pragma unroll
            for (int j = 0; j < 8; j++) acc[h][p][j] = 0ULL;

    const float* xb = x + (size_t)b * C_ * HW_ + p0;

    for (int c0i = 0; c0i < 192; c0i += 16) {
        #pragma unroll
        for (int i = 0; i < 4; i++) {
            int lin = tid + i * 256;
            int cc = lin >> 6, q4 = lin & 63;
            ((float4*)sX[cc])[q4] = *(const float4*)(xb + (size_t)(c0i + cc) * HW_ + q4 * 4);
        }
        #pragma unroll
        for (int i = 0; i < 4; i++) {
            int lin = tid + i * 256;
            int cc = lin >> 6, gg = lin & 63;
            float w = g_Wc[(c0i + cc) * 192 + g0 + gg];
            sWd[cc][gg] = make_float2(w, w);
        }
        __syncthreads();
        #pragma unroll
        for (int cc = 0; cc < 16; cc++) {
            longlong2 xA = *(const longlong2*)&sX[cc][4 * tx];
            longlong2 xB = *(const longlong2*)&sX[cc][128 + 4 * tx];
            const longlong2* wp = (const longlong2*)&sWd[cc][8 * ty];
            longlong2 w01 = wp[0], w23 = wp[1], w45 = wp[2], w67 = wp[3];
            u64 wd[8] = { (u64)w01.x, (u64)w01.y, (u64)w23.x, (u64)w23.y,
                          (u64)w45.x, (u64)w45.y, (u64)w67.x, (u64)w67.y };
            #pragma unroll
            for (int j = 0; j < 8; j++) {
                fma2(acc[0][0][j], wd[j], (u64)xA.x);
                fma2(acc[0][1][j], wd[j], (u64)xA.y);
                fma2(acc[1][0][j], wd[j], (u64)xB.x);
                fma2(acc[1][1][j], wd[j], (u64)xB.y);
            }
        }
        __syncthreads();
    }

    float bc[8];
    *(float4*)&bc[0] = *(const float4*)&g_bc[g0 + 8 * ty];
    *(float4*)&bc[4] = *(const float4*)&g_bc[g0 + 8 * ty + 4];

    #pragma unroll
    for (int h = 0; h < 2; h++) {
        #pragma unroll
        for (int p = 0; p < 2; p++) {
            const size_t q = (size_t)b * HW_ + p0 + h * 128 + 4 * tx + 2 * p;
            float2 v[8];
            #pragma unroll
            for (int j = 0; j < 8; j++) v[j] = unpack2(acc[h][p][j]);
            uint4 s0, s1;
            s0.x = h2u(__floats2half2_rn(v[0].x + bc[0], v[1].x + bc[1]));
            s0.y = h2u(__floats2half2_rn(v[2].x + bc[2], v[3].x + bc[3]));
            s0.z = h2u(__floats2half2_rn(v[4].x + bc[4], v[5].x + bc[5]));
            s0.w = h2u(__floats2half2_rn(v[6].x + bc[6], v[7].x + bc[7]));
            s1.x = h2u(__floats2half2_rn(v[0].y + bc[0], v[1].y + bc[1]));
            s1.y = h2u(__floats2half2_rn(v[2].y + bc[2], v[3].y + bc[3]));
            s1.z = h2u(__floats2half2_rn(v[4].y + bc[4], v[5].y + bc[5]));
            s1.w = h2u(__floats2half2_rn(v[6].y + bc[6], v[7].y + bc[7]));
            *(uint4*)(&g_G[q * 192 + g0 + 8 * ty])       = s0;
            *(uint4*)(&g_G[(q + 1) * 192 + g0 + 8 * ty]) = s1;
        }
    }
}

// ---------------- kernel 3: GRU scans — split-row partial sums, no shuffles ----------------
// 1024 blocks (both axes), 384 threads, 2 lines x (fwd+bwd) = 4 seqs per block.
// Thread tid: g = tid>>1 (gate row), half = tid&1 owns W_hh[g][32*half..+32) (16 u64 = 32 regs).
// Per step: 4 half-dot chains (16-deep fma2); partials -> smem hgp[s][g][half];
// gate threads (tid<256) combine halves + b_hh, compute gates, write h (double-buffered)
// and accumulate into smem line buffers (flushed coalesced at the end).
__global__ void __launch_bounds__(384, 2) scan_kernel(const float* __restrict__ Whh,
                                                      const float* __restrict__ bhh) {
    extern __shared__ __align__(16) float smem[];
    float* h2  = smem;                 // [2][4][64]  double-buffered hidden (512)
    float* hgp = smem + 512;           // [4][192][2] partial dots (1536)
    float* buf = smem + 2048;          // [2][128][64] line accumulators (16384)

    const int blk   = blockIdx.x;
    const int axis  = blk >> 9;
    const int lb    = (blk & 511) * 2;
    const int b     = lb >> 7;
    const int lane0 = lb & 127;
    const int tid   = threadIdx.x;
    const int g     = tid >> 1;
    const int half  = tid & 1;

    // 32 weights (16 u64): W_hh[g][32*half .. 32*half+31]
    u64 w2[16];
    {
        const float2* wr = (const float2*)(Whh + g * 64 + half * 32);
        #pragma unroll
        for (int k = 0; k < 16; k++) { float2 w = wr[k]; w2[k] = pack2(w.x, w.y); }
    }

    for (int i = tid; i < 512; i += 384) h2[i] = 0.f;
    __syncthreads();

    const __half* Gb = g_G + (size_t)b * HW_ * 192;
    float* outS = g_Hs[axis] + (size_t)b * HW_ * 64;

    // gate item (threads tid<256): s = tid>>6, d = tid&63
    const bool gate_on = (tid < 256);
    const int s_it  = (tid >> 6) & 3;
    const int d_it  = tid & 63;
    const int dir   = s_it & 1;
    const int li    = s_it >> 1;
    const int line  = lane0 + li;
    const int pm    = axis ? 128 : 1;
    const int pa    = axis ? line : line * 128;

    float b_r = 0.f, b_z = 0.f, b_n = 0.f;
    if (gate_on) { b_r = bhh[d_it]; b_z = bhh[64 + d_it]; b_n = bhh[128 + d_it]; }

    // initial G load (t=0)
    float cx = 0.f, cz = 0.f, cn = 0.f;
    if (gate_on) {
        const int tt = dir ? 127 : 0;
        const __half* Gp = Gb + (size_t)(pa + tt * pm) * 192 + d_it;
        cx = __half2float(__ldg(Gp));
        cz = __half2float(__ldg(Gp + 64));
        cn = __half2float(__ldg(Gp + 128));
    }

    const int half32 = half * 32;

    for (int t = 0; t < 128; t++) {
        const int cur = (t & 1) * 256;
        const int nxt = 256 - cur;

        // ---- prefetch G for step t+1 (overlaps matvec) ----
        float nx = 0.f, nz = 0.f, nn = 0.f;
        if (gate_on) {
            const int tq = (t + 1) & 127;
            const int tt = dir ? 127 - tq : tq;
            const __half* Gp = Gb + (size_t)(pa + tt * pm) * 192 + d_it;
            nx = __half2float(__ldg(Gp));
            nz = __half2float(__ldg(Gp + 64));
            nn = __half2float(__ldg(Gp + 128));
        }

        // ---- half-dot matvec: 4 independent 16-deep fma2 chains ----
        u64 a0 = 0ULL, a1 = 0ULL, a2 = 0ULL, a3 = 0ULL;
        {
            const longlong2* p0 = (const longlong2*)(h2 + cur + 0 * 64 + half32);
            const longlong2* p1 = (const longlong2*)(h2 + cur + 1 * 64 + half32);
            const longlong2* p2 = (const longlong2*)(h2 + cur + 2 * 64 + half32);
            const longlong2* p3 = (const longlong2*)(h2 + cur + 3 * 64 + half32);
            #pragma unroll
            for (int kk = 0; kk < 8; kk++) {
                longlong2 q0 = p0[kk], q1 = p1[kk], q2 = p2[kk], q3 = p3[kk];
                const u64 wA = w2[2 * kk], wB = w2[2 * kk + 1];
                fma2(a0, wA, (u64)q0.x); fma2(a1, wA, (u64)q1.x);
                fma2(a2, wA, (u64)q2.x); fma2(a3, wA, (u64)q3.x);
                fma2(a0, wB, (u64)q0.y); fma2(a1, wB, (u64)q1.y);
                fma2(a2, wB, (u64)q2.y); fma2(a3, wB, (u64)q3.y);
            }
        }
        {
            float2 f;
            const int base = 2 * g + half;
            f = unpack2(a0); hgp[0 * 384 + base] = f.x + f.y;
            f = unpack2(a1); hgp[1 * 384 + base] = f.x + f.y;
            f = unpack2(a2); hgp[2 * 384 + base] = f.x + f.y;
            f = unpack2(a3); hgp[3 * 384 + base] = f.x + f.y;
        }
        __syncthreads();

        // ---- gate phase (one item per thread, tid<256) ----
        if (gate_on) {
            const float2* hgrow = (const float2*)hgp + s_it * 192;
            const float2 pr = hgrow[d_it];
            const float2 pz = hgrow[64 + d_it];
            const float2 pn = hgrow[128 + d_it];
            const float rr = sigm(cx + pr.x + pr.y + b_r);
            const float zz = sigm(cz + pz.x + pz.y + b_z);
            const float pre = cn + rr * (pn.x + pn.y + b_n);
            const float nv = tanhx(pre);
            const float hold = h2[cur + s_it * 64 + d_it];
            const float hnew = (1.f - zz) * nv + zz * hold;
            h2[nxt + s_it * 64 + d_it] = hnew;
            const int tt = dir ? 127 - t : t;
            float* o = buf + li * 8192 + tt * 64 + d_it;
            if (t < 64) *o = hnew;        // first contribution to this pixel
            else        *o = *o + hnew;   // second contribution (smem accumulate)
        }
        __syncthreads();

        cx = nx; cz = nz; cn = nn;
    }

    // ---- flush line buffers to g_Hs (coalesced) ----
    for (int i = tid; i < 2 * 128 * 64; i += 384) {
        const int lii = i >> 13;
        const int rem = i & 8191;
        const int tt = rem >> 6;
        const int d = rem & 63;
        const int ln = lane0 + lii;
        const int p = axis ? (tt * 128 + ln) : (ln * 128 + tt);
        outS[(size_t)p * 64 + d] = buf[i];
    }
}

// ---------------- kernel 4: out = Wo @ avg(h) + bo ----------------
__global__ void __launch_bounds__(256) out_gemm_kernel(const float* __restrict__ bo,
                                                       float* __restrict__ out) {
    const int bx = blockIdx.x;
    const int b  = bx >> 8;
    const int p0 = (bx & 255) * 64;
    const int c0 = blockIdx.y * 64;
    const int tid = threadIdx.x;
    const int tx = tid & 15;
    const int ty = tid >> 4;

    __shared__ __align__(16) float sH[64][66];
    __shared__ __align__(16) float sW[64][64];

    const size_t base = ((size_t)b * HW_ + p0) * 64;
    const float* hH = g_Hs[0] + base;
    const float* hV = g_Hs[1] + base;

    #pragma unroll
    for (int i = 0; i < 16; i++) {
        int lin = tid + i * 256;
        int pp = lin >> 6, dd = lin & 63;
        sH[dd][pp] = 0.25f * (hH[(size_t)pp * 64 + dd] + hV[(size_t)pp * 64 + dd]);
    }
    #pragma unroll
    for (int i = 0; i < 16; i++) {
        int lin = tid + i * 256;
        int dd = lin >> 6, cc = lin & 63;
        sW[dd][cc] = g_Wot[dd * 192 + c0 + cc];
    }
    __syncthreads();

    u64 acc[4][2];
    #pragma unroll
    for (int j = 0; j < 4; j++) { acc[j][0] = 0ULL; acc[j][1] = 0ULL; }

    #pragma unroll
    for (int dd = 0; dd < 64; dd++) {
        const u64* ap = (const u64*)&sH[dd][4 * tx];
        u64 aLo = ap[0], aHi = ap[1];
        float4 wv = *(const float4*)&sW[dd][4 * ty];
        u64 wd[4] = { pack2(wv.x, wv.x), pack2(wv.y, wv.y),
                      pack2(wv.z, wv.z), pack2(wv.w, wv.w) };
        #pragma unroll
        for (int j = 0; j < 4; j++) {
            fma2(acc[j][0], wd[j], aLo);
            fma2(acc[j][1], wd[j], aHi);
        }
    }

    #pragma unroll
    for (int j = 0; j < 4; j++) {
        const int c = c0 + 4 * ty + j;
        const float bv = bo[c];
        float2 lo = unpack2(acc[j][0]), hi = unpack2(acc[j][1]);
        float4 v = make_float4(lo.x + bv, lo.y + bv, hi.x + bv, hi.y + bv);
        *(float4*)&out[((size_t)b * 192 + c) * HW_ + p0 + 4 * tx] = v;
    }
}

// ---------------- launch ----------------
extern "C" void kernel_launch(void* const* d_in, const int* in_sizes, int n_in,
                              void* d_out, int out_size) {
    const float* x   = (const float*)d_in[0];
    const float* Wi  = (const float*)d_in[1];
    const float* bi  = (const float*)d_in[2];
    const float* Wih = (const float*)d_in[3];
    const float* Whh = (const float*)d_in[4];
    const float* bih = (const float*)d_in[5];
    const float* bhh = (const float*)d_in[6];
    const float* Wo  = (const float*)d_in[7];
    const float* bo  = (const float*)d_in[8];
    float* out = (float*)d_out;

    const int SCAN_SMEM = (512 + 1536 + 2 * 128 * 64) * 4;   // 73728 B
    cudaFuncSetAttribute(scan_kernel, cudaFuncAttributeMaxDynamicSharedMemorySize, SCAN_SMEM);

    prep_kernel<<<256, 192>>>(Wi, bi, Wih, bih, Wo);
    g_gemm_kernel<<<dim3(3, 512), 256>>>(x);
    scan_kernel<<<1024, 384, SCAN_SMEM>>>(Whh, bhh);
    out_gemm_kernel<<<dim3(2048, 3), 256>>>(bo, out);
}

// round 12
// speedup vs baseline: 1.2273x; 1.1642x over previous
#include <cuda_runtime.h>
#include <cuda_fp16.h>
#include <cstdint>
#include <cstddef>

#define B_   8
#define C_   192
#define HW_  16384
#define D_   64

typedef unsigned long long u64;
typedef unsigned int u32;

__device__ __half g_G[(size_t)B_ * HW_ * 192];
__device__ float  g_Hs[2][(size_t)B_ * HW_ * D_];
__device__ float  g_Wc[C_ * 192];
__device__ float  g_bc[192];
__device__ float  g_Wot[D_ * C_];

__device__ __forceinline__ void fma2(u64 &acc, u64 a, u64 b) {
    asm("fma.rn.f32x2 %0, %1, %2, %0;" : "+l"(acc) : "l"(a), "l"(b));
}
__device__ __forceinline__ u64 pack2(float x, float y) {
    u64 r; asm("mov.b64 %0, {%1, %2};" : "=l"(r) : "f"(x), "f"(y)); return r;
}
__device__ __forceinline__ float2 unpack2(u64 v) {
    float2 r; asm("mov.b64 {%0, %1}, %2;" : "=f"(r.x), "=f"(r.y) : "l"(v)); return r;
}
__device__ __forceinline__ float sigm(float x) {
    float e; asm("ex2.approx.f32 %0, %1;" : "=f"(e) : "f"(-1.442695041f * x));
    float r; asm("rcp.approx.f32 %0, %1;" : "=f"(r) : "f"(1.f + e));
    return r;
}
__device__ __forceinline__ float tanhx(float x) {
    float r; asm("tanh.approx.f32 %0, %1;" : "=f"(r) : "f"(x)); return r;
}
__device__ __forceinline__ u32 h2u(__half2 h) { return *reinterpret_cast<u32*>(&h); }

__global__ void prep_kernel(const float* __restrict__ Wi, const float* __restrict__ bi,
                            const float* __restrict__ Wih, const float* __restrict__ bih,
                            const float* __restrict__ Wo) {
    const int bid = blockIdx.x;
    const int c = threadIdx.x;
    if (bid < 192) {
        const int g = bid;
        float acc = 0.f;
        #pragma unroll 8
        for (int d = 0; d < 64; d++) acc += Wih[g * 64 + d] * Wi[d * 192 + c];
        g_Wc[c * 192 + g] = acc;
        if (c == 0) {
            float s = bih[g];
            for (int d = 0; d < 64; d++) s += Wih[g * 64 + d] * bi[d];
            g_bc[g] = s;
        }
    } else {
        const int d = bid - 192;
        g_Wot[d * 192 + c] = Wo[c * 64 + d];
    }
}

__global__ void __launch_bounds__(256) g_gemm_kernel(const float* __restrict__ x) {
    const int pblk = blockIdx.y;
    const int b  = pblk >> 6;
    const int p0 = (pblk & 63) * 256;
    const int g0 = blockIdx.x * 64;
    const int tid = threadIdx.x;
    const int tx = tid & 31;
    const int ty = tid >> 5;

    __shared__ __align__(16) float  sX[16][256];
    __shared__ __align__(16) float2 sWd[16][64];

    u64 acc[2][2][8];
    #pragma unroll
    for (int h = 0; h < 2; h++)
        #pragma unroll
        for (int p = 0; p < 2; p++)
            #pragma unroll
            for (int j = 0; j < 8; j++) acc[h][p][j] = 0ULL;

    const float* xb = x + (size_t)b * C_ * HW_ + p0;

    for (int c0i = 0; c0i < 192; c0i += 16) {
        #pragma unroll
        for (int i = 0; i < 4; i++) {
            int lin = tid + i * 256;
            int cc = lin >> 6, q4 = lin & 63;
            ((float4*)sX[cc])[q4] = *(const float4*)(xb + (size_t)(c0i + cc) * HW_ + q4 * 4);
        }
        #pragma unroll
        for (int i = 0; i < 4; i++) {
            int lin = tid + i * 256;
            int cc = lin >> 6, gg = lin & 63;
            float w = g_Wc[(c0i + cc) * 192 + g0 + gg];
            sWd[cc][gg] = make_float2(w, w);
        }
        __syncthreads();
        #pragma unroll
        for (int cc = 0; cc < 16; cc++) {
            longlong2 xA = *(const longlong2*)&sX[cc][4 * tx];
            longlong2 xB = *(const longlong2*)&sX[cc][128 + 4 * tx];
            const longlong2* wp = (const longlong2*)&sWd[cc][8 * ty];
            longlong2 w01 = wp[0], w23 = wp[1], w45 = wp[2], w67 = wp[3];
            u64 wd[8] = { (u64)w01.x, (u64)w01.y, (u64)w23.x, (u64)w23.y,
                          (u64)w45.x, (u64)w45.y, (u64)w67.x, (u64)w67.y };
            #pragma unroll
            for (int j = 0; j < 8; j++) {
                fma2(acc[0][0][j], wd[j], (u64)xA.x);
                fma2(acc[0][1][j], wd[j], (u64)xA.y);
                fma2(acc[1][0][j], wd[j], (u64)xB.x);
                fma2(acc[1][1][j], wd[j], (u64)xB.y);
            }
        }
        __syncthreads();
    }

    float bc[8];
    *(float4*)&bc[0] = *(const float4*)&g_bc[g0 + 8 * ty];
    *(float4*)&bc[4] = *(const float4*)&g_bc[g0 + 8 * ty + 4];

    #pragma unroll
    for (int h = 0; h < 2; h++) {
        #pragma unroll
        for (int p = 0; p < 2; p++) {
            const size_t q = (size_t)b * HW_ + p0 + h * 128 + 4 * tx + 2 * p;
            float2 v[8];
            #pragma unroll
            for (int j = 0; j < 8; j++) v[j] = unpack2(acc[h][p][j]);
            uint4 s0, s1;
            s0.x = h2u(__floats2half2_rn(v[0].x + bc[0], v[1].x + bc[1]));
            s0.y = h2u(__floats2half2_rn(v[2].x + bc[2], v[3].x + bc[3]));
            s0.z = h2u(__floats2half2_rn(v[4].x + bc[4], v[5].x + bc[5]));
            s0.w = h2u(__floats2half2_rn(v[6].x + bc[6], v[7].x + bc[7]));
            s1.x = h2u(__floats2half2_rn(v[0].y + bc[0], v[1].y + bc[1]));
            s1.y = h2u(__floats2half2_rn(v[2].y + bc[2], v[3].y + bc[3]));
            s1.z = h2u(__floats2half2_rn(v[4].y + bc[4], v[5].y + bc[5]));
            s1.w = h2u(__floats2half2_rn(v[6].y + bc[6], v[7].y + bc[7]));
            *(uint4*)(&g_G[q * 192 + g0 + 8 * ty])       = s0;
            *(uint4*)(&g_G[(q + 1) * 192 + g0 + 8 * ty]) = s1;
        }
    }
}

// ---- scan: 1 line (fwd+bwd) per block, 192 threads, 4 blocks/SM target ----
__global__ void __launch_bounds__(192, 4) scan_kernel(const float* __restrict__ Whh,
                                                      const float* __restrict__ bhh) {
    __shared__ __align__(16) float h2[2][2][64];
    __shared__ float hg[2][192];
    __shared__ float buf[128 * 64];

    const int blk  = blockIdx.x;
    const int axis = blk >> 10;
    const int ll   = blk & 1023;
    const int b    = ll >> 7;
    const int line = ll & 127;
    const int g    = threadIdx.x;

    u64 w2[32];
    {
        const float2* wr = (const float2*)(Whh + g * 64);
        #pragma unroll
        for (int k = 0; k < 32; k++) { float2 w = wr[k]; w2[k] = pack2(w.x, w.y); }
    }
    const float bh = bhh[g];

    for (int i = g; i < 256; i += 192) ((float*)h2)[i] = 0.f;
    __syncthreads();

    const __half* Gb = g_G + (size_t)b * HW_ * 192;
    float* outS = g_Hs[axis] + (size_t)b * HW_ * 64;

    const bool gate_on = (g < 128);
    const int s_it = g >> 6;
    const int d_it = g & 63;
    const int pm   = axis ? 128 : 1;
    const int pa   = axis ? line : line * 128;

    float cx = 0.f, cz = 0.f, cn = 0.f;
    if (gate_on) {
        const int tt = s_it ? 127 : 0;
        const __half* Gp = Gb + (size_t)(pa + tt * pm) * 192 + d_it;
        cx = __half2float(__ldg(Gp));
        cz = __half2float(__ldg(Gp + 64));
        cn = __half2float(__ldg(Gp + 128));
    }

    for (int t = 0; t < 128; t++) {
        const int cur = (t & 1);
        const int nxt = cur ^ 1;

        float nx = 0.f, nz = 0.f, nn = 0.f;
        if (gate_on) {
            const int tq = (t + 1) & 127;
            const int tt = s_it ? 127 - tq : tq;
            const __half* Gp = Gb + (size_t)(pa + tt * pm) * 192 + d_it;
            nx = __half2float(__ldg(Gp));
            nz = __half2float(__ldg(Gp + 64));
            nn = __half2float(__ldg(Gp + 128));
        }

        u64 a0 = 0ULL, a1 = 0ULL;
        {
            const longlong2* p0 = (const longlong2*)h2[cur][0];
            const longlong2* p1 = (const longlong2*)h2[cur][1];
            #pragma unroll
            for (int kk = 0; kk < 16; kk++) {
                longlong2 q0 = p0[kk], q1 = p1[kk];
                const u64 wA = w2[2 * kk], wB = w2[2 * kk + 1];
                fma2(a0, wA, (u64)q0.x); fma2(a1, wA, (u64)q1.x);
                fma2(a0, wB, (u64)q0.y); fma2(a1, wB, (u64)q1.y);
            }
        }
        {
            float2 f;
            f = unpack2(a0); hg[0][g] = bh + f.x + f.y;
            f = unpack2(a1); hg[1][g] = bh + f.x + f.y;
        }
        __syncthreads();

        if (gate_on) {
            const float rr = sigm(cx + hg[s_it][d_it]);
            const float zz = sigm(cz + hg[s_it][64 + d_it]);
            const float pre = cn + rr * hg[s_it][128 + d_it];
            const float nv = tanhx(pre);
            const float hold = h2[cur][s_it][d_it];
            const float hnew = (1.f - zz) * nv + zz * hold;
            h2[nxt][s_it][d_it] = hnew;
            const int tt = s_it ? 127 - t : t;
            float* o = buf + tt * 64 + d_it;
            if (t < 64) *o = hnew;
            else        *o = *o + hnew;
        }
        __syncthreads();

        cx = nx; cz = nz; cn = nn;
    }

    for (int i = g; i < 128 * 64; i += 192) {
        const int tt = i >> 6;
        const int d = i & 63;
        const int p = axis ? (tt * 128 + line) : (line * 128 + tt);
        outS[(size_t)p * 64 + d] = buf[i];
    }
}

// NOTE: p0/p1 use longlong2 (16B) indices kk∈[0,16) — but [2][64] floats = 32
// longlong2 per seq... kk covers 16×4=64 floats ✓ (16 × 16B = 256B = 64 floats).

__global__ void __launch_bounds__(256) out_gemm_kernel(const float* __restrict__ bo,
                                                       float* __restrict__ out) {
    const int bx = blockIdx.x;
    const int b  = bx >> 8;
    const int p0 = (bx & 255) * 64;
    const int c0 = blockIdx.y * 64;
    const int tid = threadIdx.x;
    const int tx = tid & 15;
    const int ty = tid >> 4;

    __shared__ __align__(16) float sH[64][66];
    __shared__ __align__(16) float sW[64][64];

    const size_t base = ((size_t)b * HW_ + p0) * 64;
    const float* hH = g_Hs[0] + base;
    const float* hV = g_Hs[1] + base;

    #pragma unroll
    for (int i = 0; i < 16; i++) {
        int lin = tid + i * 256;
        int pp = lin >> 6, dd = lin & 63;
        sH[dd][pp] = 0.25f * (hH[(size_t)pp * 64 + dd] + hV[(size_t)pp * 64 + dd]);
    }
    #pragma unroll
    for (int i = 0; i < 16; i++) {
        int lin = tid + i * 256;
        int dd = lin >> 6, cc = lin & 63;
        sW[dd][cc] = g_Wot[dd * 192 + c0 + cc];
    }
    __syncthreads();

    u64 acc[4][2];
    #pragma unroll
    for (int j = 0; j < 4; j++) { acc[j][0] = 0ULL; acc[j][1] = 0ULL; }

    #pragma unroll
    for (int dd = 0; dd < 64; dd++) {
        const u64* ap = (const u64*)&sH[dd][4 * tx];
        u64 aLo = ap[0], aHi = ap[1];
        float4 wv = *(const float4*)&sW[dd][4 * ty];
        u64 wd[4] = { pack2(wv.x, wv.x), pack2(wv.y, wv.y),
                      pack2(wv.z, wv.z), pack2(wv.w, wv.w) };
        #pragma unroll
        for (int j = 0; j < 4; j++) {
            fma2(acc[j][0], wd[j], aLo);
            fma2(acc[j][1], wd[j], aHi);
        }
    }

    #pragma unroll
    for (int j = 0; j < 4; j++) {
        const int c = c0 + 4 * ty + j;
        const float bv = bo[c];
        float2 lo = unpack2(acc[j][0]), hi = unpack2(acc[j][1]);
        float4 v = make_float4(lo.x + bv, lo.y + bv, hi.x + bv, hi.y + bv);
        *(float4*)&out[((size_t)b * 192 + c) * HW_ + p0 + 4 * tx] = v;
    }
}

extern "C" void kernel_launch(void* const* d_in, const int* in_sizes, int n_in,
                              void* d_out, int out_size) {
    const float* x   = (const float*)d_in[0];
    const float* Wi  = (const float*)d_in[1];
    const float* bi  = (const float*)d_in[2];
    const float* Wih = (const float*)d_in[3];
    const float* Whh = (const float*)d_in[4];
    const float* bih = (const float*)d_in[5];
    const float* bhh = (const float*)d_in[6];
    const float* Wo  = (const float*)d_in[7];
    const float* bo  = (const float*)d_in[8];
    float* out = (float*)d_out;

    prep_kernel<<<256, 192>>>(Wi, bi, Wih, bih, Wo);
    g_gemm_kernel<<<dim3(3, 512), 256>>>(x);
    scan_kernel<<<2048, 192>>>(Whh, bhh);
    out_gemm_kernel<<<dim3(2048, 3), 256>>>(bo, out);
}